// round 11
// baseline (speedup 1.0000x reference)
#include <cuda_runtime.h>
#include <math.h>

#define GRIDN 17
#define NV    289
#define NF    512
#define IMG   128
#define KF    8

// block = 16x8 pixel region, 128 threads, 128 blocks (<=1 per SM)
#define RGN_W     16
#define RGN_H     8
#define BLKX      8        // 128/16
#define BLKY      16       // 128/8
#define NBLK      128
#define NTHR      128
#define TCAP      96

__device__ __forceinline__ int vid(int y, int x) { return y * GRIDN + x; }

__device__ __forceinline__ void face_idx(int f, int& i0, int& i1, int& i2) {
    int g = f >> 6, t = f & 63;
    int r = t >> 3, c = t & 7;
    int ny, nx;
    switch (g) {
        case 0:  ny = 2*r;   nx = 1+2*c; i0 = vid(ny,nx+1);   i1 = vid(ny,nx);   i2 = vid(ny+1,nx);   break;
        case 1:  ny = 2*r;   nx = 1+2*c; i0 = vid(ny,nx+1);   i1 = vid(ny+1,nx); i2 = vid(ny+1,nx+1); break;
        case 2:  ny = 2*r;   nx = 2*c;   i0 = vid(ny,nx+1);   i1 = vid(ny,nx);   i2 = vid(ny+1,nx+1); break;
        case 3:  ny = 2*r;   nx = 2*c;   i0 = vid(ny+1,nx+1); i1 = vid(ny,nx);   i2 = vid(ny+1,nx);   break;
        case 4:  ny = 1+2*r; nx = 2*c;   i0 = vid(ny,nx+1);   i1 = vid(ny,nx);   i2 = vid(ny+1,nx);   break;
        case 5:  ny = 1+2*r; nx = 2*c;   i0 = vid(ny,nx+1);   i1 = vid(ny+1,nx); i2 = vid(ny+1,nx+1); break;
        case 6:  ny = 1+2*r; nx = 1+2*c; i0 = vid(ny,nx+1);   i1 = vid(ny,nx);   i2 = vid(ny+1,nx+1); break;
        default: ny = 1+2*r; nx = 1+2*c; i0 = vid(ny+1,nx+1); i1 = vid(ny,nx);   i2 = vid(ny+1,nx);   break;
    }
}

__device__ __forceinline__ float seg_d2(float px, float py,
                                        float sx, float sy, float ex, float ey) {
    float dx = ex - sx, dy = ey - sy;
    float dd = fmaxf(dx*dx + dy*dy, 1e-12f);
    float tt = __fdividef((px - sx)*dx + (py - sy)*dy, dd);
    tt = fminf(fmaxf(tt, 0.0f), 1.0f);
    float qx = px - (sx + tt*dx), qy = py - (sy + tt*dy);
    return qx*qx + qy*qy;
}

// ---------------------------------------------------------------------------
// Fused kernel: <<<128, 128>>>.  One 16x8 pixel region per block.
// ---------------------------------------------------------------------------
__global__ void __launch_bounds__(NTHR) fused_kernel(
                             const float* __restrict__ xy_off,   // (1,289,2)
                             const float* __restrict__ z_grid,   // (1,289,1)
                             const float* __restrict__ tex,      // (1,128,128,3)
                             const float* __restrict__ R_in,     // (1,3,3)
                             const float* __restrict__ T_in,     // (1,3)
                             const float* __restrict__ R_out,    // (1,3,3)
                             const float* __restrict__ T_out,    // (1,3)
                             float* __restrict__ out)            // (1,128,128,5)
{
    const float SCALE = 0.57735026918962573f;   // tan(30 deg)
    const float SINV  = 1.0f / 0.57735026918962573f;

    __shared__ float  ssx[NV], ssy[NV], ssz[NV];
    __shared__ float4 sq[TCAP * 6];
    __shared__ int    s_cnt;

    int b  = blockIdx.x;
    int bx = b & (BLKX - 1), by = b >> 3;
    int t  = threadIdx.x;

    if (t == 0) s_cnt = 0;

    // ---- camera params (broadcast loads, batched) ----
    float ri0=R_in[0], ri1=R_in[1], ri2=R_in[2], ri3=R_in[3], ri4=R_in[4];
    float ri5=R_in[5], ri6=R_in[6], ri7=R_in[7], ri8=R_in[8];
    float ti0=T_in[0], ti1=T_in[1], ti2=T_in[2];
    float ro0=R_out[0], ro1=R_out[1], ro2=R_out[2], ro3=R_out[3], ro4=R_out[4];
    float ro5=R_out[5], ro6=R_out[6], ro7=R_out[7], ro8=R_out[8];
    float to0=T_out[0], to1=T_out[1], to2=T_out[2];

    // ---- vertex transform: 3 predicated iters, loads batched up front ----
    float lox[3], loy[3], loz[3];
    #pragma unroll
    for (int it = 0; it < 3; it++) {
        int v = t + it * NTHR;
        if (v < NV) {
            lox[it] = xy_off[2*v + 0];
            loy[it] = xy_off[2*v + 1];
            loz[it] = z_grid[v];
        }
    }
    #pragma unroll
    for (int it = 0; it < 3; it++) {
        int v = t + it * NTHR;
        if (v < NV) {
            int vy = v / GRIDN, vx = v % GRIDN;
            float ux = -1.0f + 0.125f * (float)vx;
            float uy = -1.0f + 0.125f * (float)vy;
            float gx = (ux + lox[it]) * SCALE;
            float gy = (uy + loy[it]) * SCALE;
            float zg = loz[it];
            float q0 = gx*zg - ti0, q1 = gy*zg - ti1, q2 = zg - ti2;
            float wx = ri0*q0 + ri1*q1 + ri2*q2;
            float wy = ri3*q0 + ri4*q1 + ri5*q2;
            float wz = ri6*q0 + ri7*q1 + ri8*q2;
            float vxv = wx*ro0 + wy*ro3 + wz*ro6 + to0;
            float vyv = wx*ro1 + wy*ro4 + wz*ro7 + to1;
            float vzv = wx*ro2 + wy*ro5 + wz*ro8 + to2;
            float zden = (vzv >= 0.0f) ? fmaxf(vzv, 0.01f) : fminf(vzv, -0.01f);
            float rz = __fdividef(1.0f, zden);
            ssx[v] = SINV * vxv * rz;
            ssy[v] = SINV * vyv * rz;
            ssz[v] = vzv;
        }
    }
    __syncthreads();

    // region NDC rect (px decreasing in x): x in [16bx, 16bx+15], y in [8by, 8by+7]
    float px_hi = 1.0f - (float)(32*bx + 1)  / 128.0f;
    float px_lo = 1.0f - (float)(32*bx + 31) / 128.0f;
    float py_hi = 1.0f - (float)(16*by + 1)  / 128.0f;
    float py_lo = 1.0f - (float)(16*by + 15) / 128.0f;

    // ---- cull 512 faces (4 per thread) ----
    const float M = 0.010001f;   // sqrt(BLUR_RADIUS) + eps
    #pragma unroll
    for (int it = 0; it < 4; it++) {
        int f = t + it * NTHR;
        int i0, i1, i2;
        face_idx(f, i0, i1, i2);
        float ax = ssx[i0], ay = ssy[i0];
        float bxv = ssx[i1], byv = ssy[i1];
        float cx = ssx[i2], cy = ssy[i2];
        float bbx0 = fminf(fminf(ax, bxv), cx) - M;
        float bbx1 = fmaxf(fmaxf(ax, bxv), cx) + M;
        float bby0 = fminf(fminf(ay, byv), cy) - M;
        float bby1 = fmaxf(fmaxf(ay, byv), cy) + M;
        if (bbx0 <= px_hi && bbx1 >= px_lo && bby0 <= py_hi && bby1 >= py_lo) {
            int pos = atomicAdd(&s_cnt, 1);
            if (pos < TCAP) {
                float z0 = ssz[i0], z1 = ssz[i1], z2 = ssz[i2];
                float area = (bxv - ax)*(cy - ay) - (byv - ay)*(cx - ax);
                float area_s = (fabsf(area) < 1e-8f) ? 1e-8f : area;
                float u0 = 1.0f - 0.0625f*(float)(i0 % GRIDN), v0 = 0.0625f*(float)(i0 / GRIDN);
                float u1 = 1.0f - 0.0625f*(float)(i1 % GRIDN), v1 = 0.0625f*(float)(i1 / GRIDN);
                float u2 = 1.0f - 0.0625f*(float)(i2 % GRIDN), v2 = 0.0625f*(float)(i2 / GRIDN);
                float4* q = &sq[pos * 6];
                q[0] = make_float4(bbx0, bbx1, bby0, bby1);
                q[1] = make_float4(ax, ay, bxv, byv);
                q[2] = make_float4(cx, cy, z0, z1);
                q[3] = make_float4(z2, 1.0f/area_s, z1*z2, z0*z2);
                q[4] = make_float4(z0*z1, u0, v0, u1);
                q[5] = make_float4(v1, u2, v2, __int_as_float(f));
            }
        }
    }
    __syncthreads();
    int cnt = min(s_cnt, TCAP);

    // ---- per-pixel rasterization ----
    int lx = t & (RGN_W - 1), ly = t >> 4;
    int x  = bx * RGN_W + lx;
    int y  = by * RGN_H + ly;
    float py = 1.0f - 2.0f * ((float)y + 0.5f) / 128.0f;
    float px = 1.0f - 2.0f * ((float)x + 0.5f) / 128.0f;

    float tz[KF], td[KF], tu[KF], tv[KF];
    int   ti[KF];
    #pragma unroll
    for (int k = 0; k < KF; k++) {
        tz[k] = __int_as_float(0x7f800000);
        td[k] = 0.0f; tu[k] = 0.0f; tv[k] = 0.0f; ti[k] = 0x7fffffff;
    }

    for (int i = 0; i < cnt; i++) {
        const float4* q = &sq[i * 6];
        float4 q0 = q[0];
        if (px < q0.x || px > q0.y || py < q0.z || py > q0.w) continue;

        float4 q1 = q[1], q2 = q[2], q3 = q[3], q4 = q[4], q5 = q[5];
        float ax = q1.x, ay = q1.y, bxv = q1.z, byv = q1.w;
        float cx = q2.x, cy = q2.y, z0 = q2.z, z1 = q2.w;
        float z2 = q3.x, inv_area = q3.y, z12 = q3.z, z02 = q3.w;
        float z01 = q4.x;

        float w0 = (bxv - px)*(cy - py) - (byv - py)*(cx - px);
        float w1 = (cx - px)*(ay - py) - (cy - py)*(ax - px);
        float w2 = (ax - px)*(byv - py) - (ay - py)*(bxv - px);
        float b0 = w0 * inv_area, b1 = w1 * inv_area, b2 = w2 * inv_area;
        bool inside = (b0 >= 0.0f) && (b1 >= 0.0f) && (b2 >= 0.0f);

        float n0 = b0 * z12, n1 = b1 * z02, n2 = b2 * z01;
        float den = n0 + n1 + n2;
        den = (fabsf(den) < 1e-10f) ? 1e-10f : den;
        float invden = __fdividef(1.0f, den);
        float c0 = fmaxf(n0 * invden, 0.0f);
        float c1 = fmaxf(n1 * invden, 0.0f);
        float c2 = fmaxf(n2 * invden, 0.0f);
        float invcs = __fdividef(1.0f, fmaxf(c0 + c1 + c2, 1e-10f));
        c0 *= invcs; c1 *= invcs; c2 *= invcs;
        float zpix = c0*z0 + c1*z1 + c2*z2;

        float d2 = fminf(fminf(seg_d2(px, py, ax, ay, bxv, byv),
                               seg_d2(px, py, bxv, byv, cx, cy)),
                         seg_d2(px, py, cx, cy, ax, ay));
        float sd = inside ? -d2 : d2;
        if (!((sd < 1e-4f) && (zpix > 1e-4f))) continue;

        float uu = c0*q4.y + c1*q4.w + c2*q5.y;
        float vv = c0*q4.z + c1*q5.x + c2*q5.z;
        int   f  = __float_as_int(q5.w);

        if (zpix < tz[KF-1] || (zpix == tz[KF-1] && f < ti[KF-1])) {
            float nz = zpix, nd = sd, nu = uu, nv = vv;
            int ni = f;
            #pragma unroll
            for (int k = 0; k < KF; k++) {
                bool sw = (nz < tz[k]) || (nz == tz[k] && ni < ti[k]);
                if (sw) {
                    float tf;
                    tf = tz[k]; tz[k] = nz; nz = tf;
                    tf = td[k]; td[k] = nd; nd = tf;
                    tf = tu[k]; tu[k] = nu; nu = tf;
                    tf = tv[k]; tv[k] = nv; nv = tf;
                    int tmpi = ti[k]; ti[k] = ni; ni = tmpi;
                }
            }
        }
    }

    // ---- shading epilogue (branch-free; all texture loads batchable) ----
    float prob[KF], zinv[KF], zks[KF];
    float zmax = 1e-10f;
    #pragma unroll
    for (int k = 0; k < KF; k++) {
        bool vk = (tz[k] < 1e30f);
        float sg = 1.0f / (1.0f + __expf(td[k] / 1e-4f));   // sigmoid(-d/SIGMA)
        prob[k] = vk ? sg : 0.0f;
        zks[k]  = vk ? tz[k] : 100.0f;
        zinv[k] = vk ? (100.0f - tz[k]) / 99.0f : 0.0f;
        zmax = fmaxf(zmax, zinv[k]);
    }

    // texture corner addresses + weights for all slots (no branches)
    int base00[KF], base01[KF], base10[KF], base11[KF];
    float wxx[KF], wyy[KF];
    #pragma unroll
    for (int k = 0; k < KF; k++) {
        float txc = tu[k] * 127.0f;
        float tyc = (1.0f - tv[k]) * 127.0f;
        float x0f = fminf(fmaxf(floorf(txc), 0.0f), 127.0f);
        float y0f = fminf(fmaxf(floorf(tyc), 0.0f), 127.0f);
        int x0 = (int)x0f, y0 = (int)y0f;
        int x1 = min(x0 + 1, 127), y1 = min(y0 + 1, 127);
        wxx[k] = txc - x0f;  wyy[k] = tyc - y0f;
        base00[k] = (y0 * 128 + x0) * 3;
        base01[k] = (y0 * 128 + x1) * 3;
        base10[k] = (y1 * 128 + x0) * 3;
        base11[k] = (y1 * 128 + x1) * 3;
    }

    float rs = 0.0f, gs = 0.0f, bs = 0.0f, ws = 0.0f, ds = 0.0f, oma = 1.0f;
    #pragma unroll
    for (int k = 0; k < KF; k++) {
        float w = prob[k] * __expf((zinv[k] - zmax) / 1e-4f);
        oma *= (1.0f - prob[k]);
        ws += w;
        ds += w * zks[k];
        float wx = wxx[k], wy = wyy[k];
        #pragma unroll
        for (int c = 0; c < 3; c++) {
            float top = (1.0f - wx) * __ldg(&tex[base00[k] + c]) + wx * __ldg(&tex[base01[k] + c]);
            float bot = (1.0f - wx) * __ldg(&tex[base10[k] + c]) + wx * __ldg(&tex[base11[k] + c]);
            float col = (1.0f - wy) * top + wy * bot;
            if (c == 0) rs += w * col;
            else if (c == 1) gs += w * col;
            else bs += w * col;
        }
    }

    float delta = __expf((1e-10f - zmax) / 1e-4f);
    float invd = __fdividef(1.0f, ws + delta);

    int p = y * IMG + x;
    out[p*5 + 0] = rs * invd;
    out[p*5 + 1] = gs * invd;
    out[p*5 + 2] = bs * invd;
    out[p*5 + 3] = 1.0f - oma;
    out[p*5 + 4] = (ds + delta * 100.0f) * invd;
}

// ---------------------------------------------------------------------------
extern "C" void kernel_launch(void* const* d_in, const int* in_sizes, int n_in,
                              void* d_out, int out_size) {
    const float* xy_off = (const float*)d_in[0];
    const float* z_grid = (const float*)d_in[1];
    const float* rgb_in = (const float*)d_in[2];
    const float* R_in   = (const float*)d_in[3];
    const float* T_in   = (const float*)d_in[4];
    const float* R_out  = (const float*)d_in[5];
    const float* T_out  = (const float*)d_in[6];
    float* out = (float*)d_out;

    fused_kernel<<<NBLK, NTHR>>>(xy_off, z_grid, rgb_in,
                                 R_in, T_in, R_out, T_out, out);
}

// round 14
// speedup vs baseline: 1.0983x; 1.0983x over previous
#include <cuda_runtime.h>
#include <math.h>

#define GRIDN 17
#define NV    289
#define NF    512
#define IMG   128
#define KF    8

// block = 16x8 pixel region (128 px), 2 face-lanes per pixel = 256 threads.
// 128 blocks -> 1 block/SM, 8 warps/SM.
#define RGN_W     16
#define RGN_H     8
#define BLKX      8        // 128/16
#define NBLK      128
#define NTHR      256
#define NPIX      128
#define TCAP      96

__device__ __forceinline__ int vid(int y, int x) { return y * GRIDN + x; }

__device__ __forceinline__ void face_idx(int f, int& i0, int& i1, int& i2) {
    int g = f >> 6, t = f & 63;
    int r = t >> 3, c = t & 7;
    int ny, nx;
    switch (g) {
        case 0:  ny = 2*r;   nx = 1+2*c; i0 = vid(ny,nx+1);   i1 = vid(ny,nx);   i2 = vid(ny+1,nx);   break;
        case 1:  ny = 2*r;   nx = 1+2*c; i0 = vid(ny,nx+1);   i1 = vid(ny+1,nx); i2 = vid(ny+1,nx+1); break;
        case 2:  ny = 2*r;   nx = 2*c;   i0 = vid(ny,nx+1);   i1 = vid(ny,nx);   i2 = vid(ny+1,nx+1); break;
        case 3:  ny = 2*r;   nx = 2*c;   i0 = vid(ny+1,nx+1); i1 = vid(ny,nx);   i2 = vid(ny+1,nx);   break;
        case 4:  ny = 1+2*r; nx = 2*c;   i0 = vid(ny,nx+1);   i1 = vid(ny,nx);   i2 = vid(ny+1,nx);   break;
        case 5:  ny = 1+2*r; nx = 2*c;   i0 = vid(ny,nx+1);   i1 = vid(ny+1,nx); i2 = vid(ny+1,nx+1); break;
        case 6:  ny = 1+2*r; nx = 1+2*c; i0 = vid(ny,nx+1);   i1 = vid(ny,nx);   i2 = vid(ny+1,nx+1); break;
        default: ny = 1+2*r; nx = 1+2*c; i0 = vid(ny+1,nx+1); i1 = vid(ny,nx);   i2 = vid(ny+1,nx);   break;
    }
}

__device__ __forceinline__ float seg_d2(float px, float py,
                                        float sx, float sy, float ex, float ey) {
    float dx = ex - sx, dy = ey - sy;
    float dd = fmaxf(dx*dx + dy*dy, 1e-12f);
    float tt = __fdividef((px - sx)*dx + (py - sy)*dy, dd);
    tt = fminf(fmaxf(tt, 0.0f), 1.0f);
    float qx = px - (sx + tt*dx), qy = py - (sy + tt*dy);
    return qx*qx + qy*qy;
}

// insert one (z,d,u,v,idx) candidate into a sorted-ascending top-8
__device__ __forceinline__ void top8_insert(float nz, float nd, float nu, float nv, int ni,
                                            float tz[KF], float td[KF], float tu[KF],
                                            float tv[KF], int ti[KF]) {
    if (nz < tz[KF-1] || (nz == tz[KF-1] && ni < ti[KF-1])) {
        #pragma unroll
        for (int k = 0; k < KF; k++) {
            bool sw = (nz < tz[k]) || (nz == tz[k] && ni < ti[k]);
            if (sw) {
                float tf;
                tf = tz[k]; tz[k] = nz; nz = tf;
                tf = td[k]; td[k] = nd; nd = tf;
                tf = tu[k]; tu[k] = nu; nu = tf;
                tf = tv[k]; tv[k] = nv; nv = tf;
                int tmpi = ti[k]; ti[k] = ni; ni = tmpi;
            }
        }
    }
}

// ---------------------------------------------------------------------------
// Fused kernel: <<<128, 256>>>.  One 16x8 pixel region per block,
// 2 face-lanes per pixel, merge via smem staging.
// ---------------------------------------------------------------------------
__global__ void __launch_bounds__(NTHR) fused_kernel(
                             const float* __restrict__ xy_off,   // (1,289,2)
                             const float* __restrict__ z_grid,   // (1,289,1)
                             const float* __restrict__ tex,      // (1,128,128,3)
                             const float* __restrict__ R_in,     // (1,3,3)
                             const float* __restrict__ T_in,     // (1,3)
                             const float* __restrict__ R_out,    // (1,3,3)
                             const float* __restrict__ T_out,    // (1,3)
                             float* __restrict__ out)            // (1,128,128,5)
{
    const float SCALE = 0.57735026918962573f;   // tan(30 deg)
    const float SINV  = 1.0f / 0.57735026918962573f;

    __shared__ float  ssx[NV], ssy[NV], ssz[NV];
    __shared__ float4 sq[TCAP * 6];
    __shared__ int    s_cnt;
    __shared__ float4 s_rec[NPIX * KF];   // (z, sd, u, v) lane-1 staging (16KB)
    __shared__ int    s_rix[NPIX * KF];   // face idx (4KB)

    int b  = blockIdx.x;
    int bx = b & (BLKX - 1), by = b >> 3;
    int t  = threadIdx.x;
    int p  = t & (NPIX - 1);     // pixel within region
    int l  = t >> 7;             // face lane 0/1

    if (t == 0) s_cnt = 0;

    // ---- camera params (broadcast loads) ----
    float ri0=R_in[0], ri1=R_in[1], ri2=R_in[2], ri3=R_in[3], ri4=R_in[4];
    float ri5=R_in[5], ri6=R_in[6], ri7=R_in[7], ri8=R_in[8];
    float ti0=T_in[0], ti1=T_in[1], ti2=T_in[2];
    float ro0=R_out[0], ro1=R_out[1], ro2=R_out[2], ro3=R_out[3], ro4=R_out[4];
    float ro5=R_out[5], ro6=R_out[6], ro7=R_out[7], ro8=R_out[8];
    float to0=T_out[0], to1=T_out[1], to2=T_out[2];

    // ---- vertex transform: 2 predicated iters, loads batched ----
    float lox[2], loy[2], loz[2];
    #pragma unroll
    for (int it = 0; it < 2; it++) {
        int v = t + it * NTHR;
        if (v < NV) {
            lox[it] = xy_off[2*v + 0];
            loy[it] = xy_off[2*v + 1];
            loz[it] = z_grid[v];
        }
    }
    #pragma unroll
    for (int it = 0; it < 2; it++) {
        int v = t + it * NTHR;
        if (v < NV) {
            int vy = v / GRIDN, vx = v % GRIDN;
            float ux = -1.0f + 0.125f * (float)vx;
            float uy = -1.0f + 0.125f * (float)vy;
            float gx = (ux + lox[it]) * SCALE;
            float gy = (uy + loy[it]) * SCALE;
            float zg = loz[it];
            float q0 = gx*zg - ti0, q1 = gy*zg - ti1, q2 = zg - ti2;
            float wx = ri0*q0 + ri1*q1 + ri2*q2;
            float wy = ri3*q0 + ri4*q1 + ri5*q2;
            float wz = ri6*q0 + ri7*q1 + ri8*q2;
            float vxv = wx*ro0 + wy*ro3 + wz*ro6 + to0;
            float vyv = wx*ro1 + wy*ro4 + wz*ro7 + to1;
            float vzv = wx*ro2 + wy*ro5 + wz*ro8 + to2;
            float zden = (vzv >= 0.0f) ? fmaxf(vzv, 0.01f) : fminf(vzv, -0.01f);
            float rz = __fdividef(1.0f, zden);
            ssx[v] = SINV * vxv * rz;
            ssy[v] = SINV * vyv * rz;
            ssz[v] = vzv;
        }
    }
    __syncthreads();

    // region NDC rect
    float px_hi = 1.0f - (float)(32*bx + 1)  / 128.0f;
    float px_lo = 1.0f - (float)(32*bx + 31) / 128.0f;
    float py_hi = 1.0f - (float)(16*by + 1)  / 128.0f;
    float py_lo = 1.0f - (float)(16*by + 15) / 128.0f;

    // ---- cull 512 faces (2 per thread) ----
    const float M = 0.010001f;   // sqrt(BLUR_RADIUS) + eps
    #pragma unroll
    for (int it = 0; it < 2; it++) {
        int f = t + it * NTHR;
        int i0, i1, i2;
        face_idx(f, i0, i1, i2);
        float ax = ssx[i0], ay = ssy[i0];
        float bxv = ssx[i1], byv = ssy[i1];
        float cx = ssx[i2], cy = ssy[i2];
        float bbx0 = fminf(fminf(ax, bxv), cx) - M;
        float bbx1 = fmaxf(fmaxf(ax, bxv), cx) + M;
        float bby0 = fminf(fminf(ay, byv), cy) - M;
        float bby1 = fmaxf(fmaxf(ay, byv), cy) + M;
        if (bbx0 <= px_hi && bbx1 >= px_lo && bby0 <= py_hi && bby1 >= py_lo) {
            int pos = atomicAdd(&s_cnt, 1);
            if (pos < TCAP) {
                float z0 = ssz[i0], z1 = ssz[i1], z2 = ssz[i2];
                float area = (bxv - ax)*(cy - ay) - (byv - ay)*(cx - ax);
                float area_s = (fabsf(area) < 1e-8f) ? 1e-8f : area;
                float u0 = 1.0f - 0.0625f*(float)(i0 % GRIDN), v0 = 0.0625f*(float)(i0 / GRIDN);
                float u1 = 1.0f - 0.0625f*(float)(i1 % GRIDN), v1 = 0.0625f*(float)(i1 / GRIDN);
                float u2 = 1.0f - 0.0625f*(float)(i2 % GRIDN), v2 = 0.0625f*(float)(i2 / GRIDN);
                float4* q = &sq[pos * 6];
                q[0] = make_float4(bbx0, bbx1, bby0, bby1);
                q[1] = make_float4(ax, ay, bxv, byv);
                q[2] = make_float4(cx, cy, z0, z1);
                q[3] = make_float4(z2, 1.0f/area_s, z1*z2, z0*z2);
                q[4] = make_float4(z0*z1, u0, v0, u1);
                q[5] = make_float4(v1, u2, v2, __int_as_float(f));
            }
        }
    }
    __syncthreads();
    int cnt = min(s_cnt, TCAP);

    // ---- per-pixel rasterization, faces split across 2 lanes ----
    int lx = p & (RGN_W - 1), ly = p >> 4;
    int x  = bx * RGN_W + lx;
    int y  = by * RGN_H + ly;
    float py = 1.0f - 2.0f * ((float)y + 0.5f) / 128.0f;
    float px = 1.0f - 2.0f * ((float)x + 0.5f) / 128.0f;

    float tz[KF], td[KF], tu[KF], tv[KF];
    int   ti[KF];
    #pragma unroll
    for (int k = 0; k < KF; k++) {
        tz[k] = __int_as_float(0x7f800000);
        td[k] = 0.0f; tu[k] = 0.0f; tv[k] = 0.0f; ti[k] = 0x7fffffff;
    }

    for (int i = l; i < cnt; i += 2) {
        const float4* q = &sq[i * 6];
        float4 q0 = q[0];
        if (px < q0.x || px > q0.y || py < q0.z || py > q0.w) continue;

        float4 q1 = q[1], q2 = q[2], q3 = q[3], q4 = q[4], q5 = q[5];
        float ax = q1.x, ay = q1.y, bxv = q1.z, byv = q1.w;
        float cx = q2.x, cy = q2.y, z0 = q2.z, z1 = q2.w;
        float z2 = q3.x, inv_area = q3.y, z12 = q3.z, z02 = q3.w;
        float z01 = q4.x;

        float w0 = (bxv - px)*(cy - py) - (byv - py)*(cx - px);
        float w1 = (cx - px)*(ay - py) - (cy - py)*(ax - px);
        float w2 = (ax - px)*(byv - py) - (ay - py)*(bxv - px);
        float b0 = w0 * inv_area, b1 = w1 * inv_area, b2 = w2 * inv_area;
        bool inside = (b0 >= 0.0f) && (b1 >= 0.0f) && (b2 >= 0.0f);

        float n0 = b0 * z12, n1 = b1 * z02, n2 = b2 * z01;
        float den = n0 + n1 + n2;
        den = (fabsf(den) < 1e-10f) ? 1e-10f : den;
        float invden = __fdividef(1.0f, den);
        float c0 = fmaxf(n0 * invden, 0.0f);
        float c1 = fmaxf(n1 * invden, 0.0f);
        float c2 = fmaxf(n2 * invden, 0.0f);
        float invcs = __fdividef(1.0f, fmaxf(c0 + c1 + c2, 1e-10f));
        c0 *= invcs; c1 *= invcs; c2 *= invcs;
        float zpix = c0*z0 + c1*z1 + c2*z2;

        float d2 = fminf(fminf(seg_d2(px, py, ax, ay, bxv, byv),
                               seg_d2(px, py, bxv, byv, cx, cy)),
                         seg_d2(px, py, cx, cy, ax, ay));
        float sd = inside ? -d2 : d2;
        if (!((sd < 1e-4f) && (zpix > 1e-4f))) continue;

        float uu = c0*q4.y + c1*q4.w + c2*q5.y;
        float vv = c0*q4.z + c1*q5.x + c2*q5.z;
        top8_insert(zpix, sd, uu, vv, __float_as_int(q5.w), tz, td, tu, tv, ti);
    }

    // ---- merge lane 1 -> lane 0 ----
    __syncthreads();
    if (l == 1) {
        #pragma unroll
        for (int k = 0; k < KF; k++) {
            s_rec[p * KF + k] = make_float4(tz[k], td[k], tu[k], tv[k]);
            s_rix[p * KF + k] = ti[k];
        }
    }
    __syncthreads();
    if (l == 1) return;   // lane-1 warps done

    #pragma unroll
    for (int k = 0; k < KF; k++) {
        float4 r = s_rec[p * KF + k];
        int rix  = s_rix[p * KF + k];
        top8_insert(r.x, r.y, r.z, r.w, rix, tz, td, tu, tv, ti);
    }

    // ---- shading epilogue (lane 0; branch-free texture path) ----
    float prob[KF], zinv[KF], zks[KF];
    float zmax = 1e-10f;
    #pragma unroll
    for (int k = 0; k < KF; k++) {
        bool vk = (tz[k] < 1e30f);
        float sg = 1.0f / (1.0f + __expf(td[k] / 1e-4f));   // sigmoid(-d/SIGMA)
        prob[k] = vk ? sg : 0.0f;
        zks[k]  = vk ? tz[k] : 100.0f;
        zinv[k] = vk ? (100.0f - tz[k]) / 99.0f : 0.0f;
        zmax = fmaxf(zmax, zinv[k]);
    }

    int base00[KF], base01[KF], base10[KF], base11[KF];
    float wxx[KF], wyy[KF];
    #pragma unroll
    for (int k = 0; k < KF; k++) {
        float txc = tu[k] * 127.0f;
        float tyc = (1.0f - tv[k]) * 127.0f;
        float x0f = fminf(fmaxf(floorf(txc), 0.0f), 127.0f);
        float y0f = fminf(fmaxf(floorf(tyc), 0.0f), 127.0f);
        int x0 = (int)x0f, y0 = (int)y0f;
        int x1 = min(x0 + 1, 127), y1 = min(y0 + 1, 127);
        wxx[k] = txc - x0f;  wyy[k] = tyc - y0f;
        base00[k] = (y0 * 128 + x0) * 3;
        base01[k] = (y0 * 128 + x1) * 3;
        base10[k] = (y1 * 128 + x0) * 3;
        base11[k] = (y1 * 128 + x1) * 3;
    }

    float rs = 0.0f, gs = 0.0f, bs = 0.0f, ws = 0.0f, ds = 0.0f, oma = 1.0f;
    #pragma unroll
    for (int k = 0; k < KF; k++) {
        float w = prob[k] * __expf((zinv[k] - zmax) / 1e-4f);
        oma *= (1.0f - prob[k]);
        ws += w;
        ds += w * zks[k];
        float wx = wxx[k], wy = wyy[k];
        #pragma unroll
        for (int c = 0; c < 3; c++) {
            float top = (1.0f - wx) * __ldg(&tex[base00[k] + c]) + wx * __ldg(&tex[base01[k] + c]);
            float bot = (1.0f - wx) * __ldg(&tex[base10[k] + c]) + wx * __ldg(&tex[base11[k] + c]);
            float col = (1.0f - wy) * top + wy * bot;
            if (c == 0) rs += w * col;
            else if (c == 1) gs += w * col;
            else bs += w * col;
        }
    }

    float delta = __expf((1e-10f - zmax) / 1e-4f);
    float invd = __fdividef(1.0f, ws + delta);

    int pp = y * IMG + x;
    out[pp*5 + 0] = rs * invd;
    out[pp*5 + 1] = gs * invd;
    out[pp*5 + 2] = bs * invd;
    out[pp*5 + 3] = 1.0f - oma;
    out[pp*5 + 4] = (ds + delta * 100.0f) * invd;
}

// ---------------------------------------------------------------------------
extern "C" void kernel_launch(void* const* d_in, const int* in_sizes, int n_in,
                              void* d_out, int out_size) {
    const float* xy_off = (const float*)d_in[0];
    const float* z_grid = (const float*)d_in[1];
    const float* rgb_in = (const float*)d_in[2];
    const float* R_in   = (const float*)d_in[3];
    const float* T_in   = (const float*)d_in[4];
    const float* R_out  = (const float*)d_in[5];
    const float* T_out  = (const float*)d_in[6];
    float* out = (float*)d_out;

    fused_kernel<<<NBLK, NTHR>>>(xy_off, z_grid, rgb_in,
                                 R_in, T_in, R_out, T_out, out);
}